// round 15
// baseline (speedup 1.0000x reference)
#include <cuda_runtime.h>
#include <cuda_fp16.h>
#include <math.h>
#include <stdint.h>

// Problem constants
#define BB    64      // batch
#define TT    1024    // timesteps
#define HH    256     // hidden
#define NCTA  128     // persistent CTAs (each owns 2 hidden units, both layers)
#define NT    128     // threads: tid = u*64 + b

#define NCHUNK        4
#define M_PER_CHUNK   32
#define CH0_FLOATS    4096   // h0 chunk (fp32)
#define CH0_BYTES     16384
#define CH1_HALFS     4096   // h1 chunk (fp16)
#define CH1_BYTES     8192

typedef unsigned long long ull;

// Persistent device state (static allocation only)
// h layout: [pair m][batch b][e] -> idx = m*128 + b*2 + e, unit k = 2m+e
__device__ __align__(128) float          g_h0[2][HH * BB];   // fp32
__device__ __align__(128) unsigned short g_h1[2][HH * BB];   // fp16
__device__ float    g_hmean[HH * BB];       // [j*64 + b]
__device__ float    g_xT[TT * BB];          // [t*64 + b]
__device__ unsigned g_ct;                   // global barrier counter (monotonic)

// Pre-gathered per-CTA weight slices (L1-resident in the hot loop).
// Layout per CTA slice (2048 floats): float2 index (m*2+u)*4+g =
//   { W[2m][g*256+j], W[2m+1][g*256+j] },  j = cta*2+u.
__device__ __align__(128) float g_w0[NCTA * 2048];   // Wh0
__device__ __align__(128) float g_wx[NCTA * 2048];   // Wx1
__device__ __align__(128) float g_w1[NCTA * 2048];   // Wh1

// ---------------------------------------------------------------------------
__global__ void init_kernel(const float* __restrict__ x) {
    int i = blockIdx.x * blockDim.x + threadIdx.x;
    if (i == 0) g_ct = 0u;
    if (i < TT * BB) {
        int t = i >> 6;
        int b = i & 63;
        g_xT[i] = x[b * TT + t];
    }
    if (i < HH * BB) {
        g_h0[0][i] = 0.f; g_h0[1][i] = 0.f;
        g_h1[0][i] = 0;   g_h1[1][i] = 0;
    }
}

// Pre-gather weight slices into the per-CTA global layout (mirrors the
// proven smem preload loop; runs once per replay, idempotent).
__global__ void prep_weights(const float* __restrict__ Wh0,
                             const float* __restrict__ Wx1,
                             const float* __restrict__ Wh1) {
    const int bx  = blockIdx.x;
    const int tid = threadIdx.x;
    for (int idx = tid; idx < 256; idx += 128) {
        const int m  = idx >> 1;
        const int uu = idx & 1;
        const int jj = bx * 2 + uu;
        float2* d0 = (float2*)(g_w0 + bx * 2048) + idx * 4;
        float2* dx = (float2*)(g_wx + bx * 2048) + idx * 4;
        float2* d1 = (float2*)(g_w1 + bx * 2048) + idx * 4;
        const float* ra0 = Wh0 + (2 * m) * 1024;
        const float* rb0 = Wh0 + (2 * m + 1) * 1024;
        const float* rax = Wx1 + (2 * m) * 1024;
        const float* rbx = Wx1 + (2 * m + 1) * 1024;
        const float* ra1 = Wh1 + (2 * m) * 1024;
        const float* rb1 = Wh1 + (2 * m + 1) * 1024;
        #pragma unroll
        for (int g = 0; g < 4; ++g) {
            d0[g] = make_float2(ra0[g * 256 + jj], rb0[g * 256 + jj]);
            dx[g] = make_float2(rax[g * 256 + jj], rbx[g * 256 + jj]);
            d1[g] = make_float2(ra1[g * 256 + jj], rb1[g * 256 + jj]);
        }
    }
}

// ---------------------------------------------------------------------------
// helpers
// ---------------------------------------------------------------------------
__device__ __forceinline__ uint32_t smem_u32(const void* p) {
    uint32_t a;
    asm("{ .reg .u64 t; cvta.to.shared.u64 t, %1; cvt.u32.u64 %0, t; }"
        : "=r"(a) : "l"(p));
    return a;
}

__device__ __forceinline__ void fma2(ull& d, ull a, ull b) {
    asm("fma.rn.f32x2 %0, %1, %2, %0;" : "+l"(d) : "l"(a), "l"(b));
}

__device__ __forceinline__ ull pack2(float lo, float hi) {
    ull v; asm("mov.b64 %0, {%1, %2};" : "=l"(v) : "f"(lo), "f"(hi)); return v;
}

__device__ __forceinline__ float hadd2(ull v) {
    float lo, hi; asm("mov.b64 {%0, %1}, %2;" : "=f"(lo), "=f"(hi) : "l"(v));
    return lo + hi;
}

// packed half2 (as uint) -> packed f32x2 (as ull)
__device__ __forceinline__ ull h2_to_f32x2(uint32_t h2) {
    ull v;
    asm("{ .reg .b16 l, h; .reg .f32 fl, fh;\n\t"
        "mov.b32 {l, h}, %1;\n\t"
        "cvt.f32.f16 fl, l;\n\t"
        "cvt.f32.f16 fh, h;\n\t"
        "mov.b64 %0, {fl, fh}; }"
        : "=l"(v) : "r"(h2));
    return v;
}

__device__ __forceinline__ void st_h16(unsigned short* p, float f) {
    unsigned short hr = __half_as_ushort(__float2half_rn(f));
    asm volatile("st.global.cg.u16 [%0], %1;" :: "l"(p), "h"(hr) : "memory");
}

__device__ __forceinline__ void mbar_init(uint32_t a, unsigned cnt) {
    asm volatile("mbarrier.init.shared.b64 [%0], %1;" :: "r"(a), "r"(cnt) : "memory");
}

__device__ __forceinline__ void mbar_expect_tx(uint32_t a, unsigned bytes) {
    asm volatile("mbarrier.arrive.expect_tx.shared.b64 _, [%0], %1;"
                 :: "r"(a), "r"(bytes) : "memory");
}

__device__ __forceinline__ void mbar_wait(uint32_t a, unsigned parity) {
    asm volatile(
        "{\n\t.reg .pred P;\n\t"
        "WL%=:\n\t"
        "mbarrier.try_wait.parity.acquire.cta.shared::cta.b64 P, [%0], %1, 0x989680;\n\t"
        "@P bra.uni WD%=;\n\t"
        "bra.uni WL%=;\n\t"
        "WD%=:\n\t}"
        :: "r"(a), "r"(parity) : "memory");
}

__device__ __forceinline__ void bulk_g2s(uint32_t dst, const void* src,
                                         unsigned bytes, uint32_t mbar) {
    asm volatile(
        "cp.async.bulk.shared::cluster.global.mbarrier::complete_tx::bytes "
        "[%0], [%1], %2, [%3];"
        :: "r"(dst), "l"(src), "r"(bytes), "r"(mbar) : "memory");
}

__device__ __forceinline__ float sigm(float x) {
    return __fdividef(1.f, 1.f + __expf(-x));
}
__device__ __forceinline__ float tanh_f(float x) {
    float e = __expf(-2.f * fabsf(x));
    float t = __fdividef(1.f - e, 1.f + e);
    return copysignf(t, x);
}

// ---------------------------------------------------------------------------
// Persistent fused 2-layer LSTM.
// Control flow identical to R12 (best known): per-thread fence + sync, tid0
// single-counter atomic + volatile spin, tid0 issues chunked TMA, warps 1..3
// gated by chunk mbarriers.
//
// NEW: weights stream from L1-cached global (__ldg, warp-uniform 16B) instead
// of smem broadcast LDS — removes 24 of 36 crossbar phases per m, dropping the
// compute floor from 4608 (crossbar-bound) to ~3100 (FMA/issue-bound).
// h0 is fp32 (no cvt), h1 fp16 (halves its stream + crossbar phase).
// ---------------------------------------------------------------------------
__global__ void __launch_bounds__(NT, 1) lstm_persistent(
    const float* __restrict__ b0, const float* __restrict__ Wx0,
    const float* __restrict__ b1)
{
    extern __shared__ char smem[];
    // bytes: sh0[65536] fp32 | sh1[32768] fp16 | mbars
    const uint32_t sbase   = smem_u32(smem);
    const uint32_t sh1_u32 = sbase + 65536;
    const uint32_t mbar_u  = sbase + 98304;

    const int tid = threadIdx.x;
    const int b   = tid & 63;
    const int u   = tid >> 6;
    const int j   = blockIdx.x * 2 + u;

    if (tid == 0) {
        #pragma unroll
        for (int c = 0; c < NCHUNK; ++c) mbar_init(mbar_u + c * 8, 1);
    }

    const float4 bia0 = make_float4(b0[j], b0[256 + j], b0[512 + j], b0[768 + j]);
    const float4 bia1 = make_float4(b1[j], b1[256 + j], b1[512 + j], b1[768 + j]);
    const float4 wx0  = make_float4(Wx0[j], Wx0[256 + j], Wx0[512 + j], Wx0[768 + j]);

    float c0 = 0.f, c1 = 0.f, hsum = 0.f;
    __syncthreads();   // mbar init visible

    // per-thread pointers
    const ull*      ph0 = (const ull*)smem + b;                       // h0 pair at ph0[m*64]
    const uint32_t* ph1 = (const uint32_t*)(smem + 65536) + b;        // h1 pair at ph1[m*64]
    const ulonglong2* pw0 = (const ulonglong2*)(g_w0 + blockIdx.x * 2048) + u * 2;
    const ulonglong2* pwx = (const ulonglong2*)(g_wx + blockIdx.x * 2048) + u * 2;
    const ulonglong2* pw1 = (const ulonglong2*)(g_w1 + blockIdx.x * 2048) + u * 2;

    const int houti = (j >> 1) * 128 + b * 2 + (j & 1);

    for (int t = 0; t <= TT; ++t) {
        if (t > 0) {
            __threadfence();      // own h stores -> L2 (parallel across threads)
            __syncthreads();      // whole CTA done with previous slot
            if (tid == 0) {
                atomicAdd(&g_ct, 1u);
                const unsigned target = (unsigned)t * NCTA;
                while (*((volatile unsigned*)&g_ct) < target) { }
            }
            // NOTE: no __syncthreads here — other threads run ahead to the
            // mbar waits, which gate on this slot's TMA completions.
        }

        if (tid == 0) {
            asm volatile("fence.proxy.async;" ::: "memory");
            const float*          s0 = g_h0[(t + 1) & 1];
            const unsigned short* s1 = g_h1[t & 1];
            #pragma unroll
            for (int c = 0; c < NCHUNK; ++c) {
                const uint32_t mb = mbar_u + c * 8;
                mbar_expect_tx(mb, CH0_BYTES + CH1_BYTES);
                bulk_g2s(sbase   + c * CH0_BYTES, s0 + c * CH0_FLOATS, CH0_BYTES, mb);
                bulk_g2s(sh1_u32 + c * CH1_BYTES, s1 + c * CH1_HALFS, CH1_BYTES, mb);
            }
        }

        // init gate accumulators (lane-lo gets bias + x-contribution)
        const float xv = (t < TT) ? g_xT[t * BB + b] : 0.f;
        ull a0i = pack2(fmaf(xv, wx0.x, bia0.x), 0.f);
        ull a0f = pack2(fmaf(xv, wx0.y, bia0.y), 0.f);
        ull a0g = pack2(fmaf(xv, wx0.z, bia0.z), 0.f);
        ull a0o = pack2(fmaf(xv, wx0.w, bia0.w), 0.f);
        ull a1i = pack2(bia1.x, 0.f);
        ull a1f = pack2(bia1.y, 0.f);
        ull a1g = pack2(bia1.z, 0.f);
        ull a1o = pack2(bia1.w, 0.f);

        const unsigned par = (unsigned)(t & 1);
        #pragma unroll
        for (int c = 0; c < NCHUNK; ++c) {
            mbar_wait(mbar_u + c * 8, par);
            const int mbase = c * M_PER_CHUNK;
            #pragma unroll 8
            for (int mm = 0; mm < M_PER_CHUNK; ++mm) {
                const int m = mbase + mm;
                const ull hv2  = ph0[m * 64];
                const ull h1v2 = h2_to_f32x2(ph1[m * 64]);
                const ulonglong2 w0a = __ldg(pw0 + m * 4);
                const ulonglong2 w0b = __ldg(pw0 + m * 4 + 1);
                fma2(a0i, hv2, w0a.x); fma2(a0f, hv2, w0a.y);
                fma2(a0g, hv2, w0b.x); fma2(a0o, hv2, w0b.y);
                const ulonglong2 wxa = __ldg(pwx + m * 4);
                const ulonglong2 wxb = __ldg(pwx + m * 4 + 1);
                fma2(a1i, hv2, wxa.x); fma2(a1f, hv2, wxa.y);
                fma2(a1g, hv2, wxb.x); fma2(a1o, hv2, wxb.y);
                const ulonglong2 w1a = __ldg(pw1 + m * 4);
                const ulonglong2 w1b = __ldg(pw1 + m * 4 + 1);
                fma2(a1i, h1v2, w1a.x); fma2(a1f, h1v2, w1a.y);
                fma2(a1g, h1v2, w1b.x); fma2(a1o, h1v2, w1b.y);
            }
        }

        if (t < TT) {   // layer0 step t
            const float ig = sigm(hadd2(a0i));
            const float fg = sigm(hadd2(a0f));
            const float gg = tanh_f(hadd2(a0g));
            const float og = sigm(hadd2(a0o));
            c0 = fmaf(fg, c0, ig * gg);
            __stcg(&g_h0[t & 1][houti], og * tanh_f(c0));
        }
        if (t > 0) {    // layer1 step t-1
            const float ig = sigm(hadd2(a1i));
            const float fg = sigm(hadd2(a1f));
            const float gg = tanh_f(hadd2(a1g));
            const float og = sigm(hadd2(a1o));
            c1 = fmaf(fg, c1, ig * gg);
            const float h1n = og * tanh_f(c1);
            hsum += h1n;
            if (t < TT) st_h16(&g_h1[(t + 1) & 1][houti], h1n);
        }
    }

    g_hmean[j * 64 + b] = hsum * (1.f / 1024.f);
}

// ---------------------------------------------------------------------------
// Head: theta projection, concat, 3x (dense + ELU), final dense. Runs once.
// ---------------------------------------------------------------------------
__global__ void final_kernel(
    const float* __restrict__ theta,
    const float* __restrict__ pW, const float* __restrict__ pb,
    const float* __restrict__ l0W, const float* __restrict__ l0b,
    const float* __restrict__ l1W, const float* __restrict__ l1b,
    const float* __restrict__ l2W, const float* __restrict__ l2b,
    const float* __restrict__ oW,  const float* __restrict__ ob,
    float* __restrict__ out)
{
    __shared__ float hin[512];
    __shared__ float act0[256];
    __shared__ float act1[256];
    __shared__ float act2[128];
    const int bb = blockIdx.x;
    const int tj = threadIdx.x;

    hin[tj] = g_hmean[tj * 64 + bb];
    {
        float s = pb[tj];
        #pragma unroll
        for (int d = 0; d < 5; ++d) s = fmaf(theta[bb * 5 + d], pW[d * 256 + tj], s);
        hin[256 + tj] = s;
    }
    __syncthreads();
    {
        float acc = l0b[tj];
        for (int k = 0; k < 512; ++k) acc = fmaf(hin[k], l0W[k * 256 + tj], acc);
        act0[tj] = acc > 0.f ? acc : expm1f(acc);
    }
    __syncthreads();
    {
        float acc = l1b[tj];
        for (int k = 0; k < 256; ++k) acc = fmaf(act0[k], l1W[k * 256 + tj], acc);
        act1[tj] = acc > 0.f ? acc : expm1f(acc);
    }
    __syncthreads();
    if (tj < 128) {
        float acc = l2b[tj];
        for (int k = 0; k < 256; ++k) acc = fmaf(act1[k], l2W[k * 128 + tj], acc);
        act2[tj] = acc > 0.f ? acc : expm1f(acc);
    }
    __syncthreads();
    if (tj == 0) {
        float s = ob[0];
        for (int k = 0; k < 128; ++k) s = fmaf(act2[k], oW[k], s);
        out[bb] = s;
    }
}

// ---------------------------------------------------------------------------
extern "C" void kernel_launch(void* const* d_in, const int* in_sizes, int n_in,
                              void* d_out, int out_size) {
    const float* x     = (const float*)d_in[0];
    const float* theta = (const float*)d_in[1];
    const float* Wx0   = (const float*)d_in[2];
    const float* Wh0   = (const float*)d_in[3];
    const float* b0    = (const float*)d_in[4];
    const float* Wx1   = (const float*)d_in[5];
    const float* Wh1   = (const float*)d_in[6];
    const float* b1    = (const float*)d_in[7];
    const float* pW    = (const float*)d_in[8];
    const float* pb    = (const float*)d_in[9];
    const float* l0W   = (const float*)d_in[10];
    const float* l0b   = (const float*)d_in[11];
    const float* l1W   = (const float*)d_in[12];
    const float* l1b   = (const float*)d_in[13];
    const float* l2W   = (const float*)d_in[14];
    const float* l2b   = (const float*)d_in[15];
    const float* oW    = (const float*)d_in[16];
    const float* ob    = (const float*)d_in[17];

    // 64K fp32 h0 stage + 32K fp16 h1 stage + mbars
    const int smem_bytes = 98304 + 64;
    cudaFuncSetAttribute(lstm_persistent,
                         cudaFuncAttributeMaxDynamicSharedMemorySize, smem_bytes);

    init_kernel<<<(TT * BB + 255) / 256, 256>>>(x);
    prep_weights<<<NCTA, 128>>>(Wh0, Wx1, Wh1);
    lstm_persistent<<<NCTA, NT, smem_bytes>>>(b0, Wx0, b1);
    final_kernel<<<BB, 256>>>(theta, pW, pb, l0W, l0b, l1W, l1b,
                              l2W, l2b, oW, ob, (float*)d_out);
}

// round 16
// speedup vs baseline: 1.8208x; 1.8208x over previous
#include <cuda_runtime.h>
#include <cuda_fp16.h>
#include <math.h>
#include <stdint.h>

// Problem constants
#define BB    64      // batch
#define TT    1024    // timesteps
#define HH    256     // hidden
#define NCTA  128     // persistent CTAs (each owns 2 hidden units, both layers)
#define NT    256     // 8 warps: warps 0-3 = k-half 0, warps 4-7 = k-half 1

#define NCHUNK       4
#define M_PER_CHUNK  32
#define CHUNK_HALFS  4096    // per h-array per chunk (fp16)
#define CHUNK_BYTES  8192

typedef unsigned long long ull;

// Persistent device state (static allocation only)
// h stored as fp16: [pair m][batch b][e] -> half idx = m*128 + b*2 + e
__device__ __align__(128) unsigned short g_h0[2][HH * BB];
__device__ __align__(128) unsigned short g_h1[2][HH * BB];
__device__ float    g_hmean[HH * BB];       // [j*64 + b]
__device__ float    g_xT[TT * BB];          // [t*64 + b]
__device__ unsigned g_ct;                   // global barrier counter (monotonic)

// smem layout (bytes)
#define SH0_OFF   0        // 32768: fp16 h0 stage
#define SH1_OFF   32768    // 32768: fp16 h1 stage
#define W0_OFF    65536    // 8192
#define WX_OFF    73728    // 8192
#define W1_OFF    81920    // 8192
#define RED_OFF   90112    // 8192: split-k reduction zone (128 x 8 ull)
#define MB_OFF    98304
#define SMEM_SZ   98368

// ---------------------------------------------------------------------------
__global__ void init_kernel(const float* __restrict__ x) {
    int i = blockIdx.x * blockDim.x + threadIdx.x;
    if (i == 0) g_ct = 0u;
    if (i < TT * BB) {
        int t = i >> 6;
        int b = i & 63;
        g_xT[i] = x[b * TT + t];
    }
    if (i < HH * BB) {
        g_h0[0][i] = 0; g_h0[1][i] = 0;   // 0x0000 == +0.0 in fp16
        g_h1[0][i] = 0; g_h1[1][i] = 0;
    }
}

// ---------------------------------------------------------------------------
// helpers
// ---------------------------------------------------------------------------
__device__ __forceinline__ uint32_t smem_u32(const void* p) {
    uint32_t a;
    asm("{ .reg .u64 t; cvta.to.shared.u64 t, %1; cvt.u32.u64 %0, t; }"
        : "=r"(a) : "l"(p));
    return a;
}

__device__ __forceinline__ void fma2(ull& d, ull a, ull b) {
    asm("fma.rn.f32x2 %0, %1, %2, %0;" : "+l"(d) : "l"(a), "l"(b));
}

__device__ __forceinline__ void add2(ull& d, ull a) {
    asm("add.rn.f32x2 %0, %0, %1;" : "+l"(d) : "l"(a));
}

__device__ __forceinline__ ull pack2(float lo, float hi) {
    ull v; asm("mov.b64 %0, {%1, %2};" : "=l"(v) : "f"(lo), "f"(hi)); return v;
}

__device__ __forceinline__ float hadd2(ull v) {
    float lo, hi; asm("mov.b64 {%0, %1}, %2;" : "=f"(lo), "=f"(hi) : "l"(v));
    return lo + hi;
}

// packed half2 (as uint) -> packed f32x2 (as ull)
__device__ __forceinline__ ull h2_to_f32x2(uint32_t h2) {
    ull v;
    asm("{ .reg .b16 l, h; .reg .f32 fl, fh;\n\t"
        "mov.b32 {l, h}, %1;\n\t"
        "cvt.f32.f16 fl, l;\n\t"
        "cvt.f32.f16 fh, h;\n\t"
        "mov.b64 %0, {fl, fh}; }"
        : "=l"(v) : "r"(h2));
    return v;
}

__device__ __forceinline__ void st_h16(unsigned short* p, float f) {
    unsigned short hr = __half_as_ushort(__float2half_rn(f));
    asm volatile("st.global.cg.u16 [%0], %1;" :: "l"(p), "h"(hr) : "memory");
}

__device__ __forceinline__ void mbar_init(uint32_t a, unsigned cnt) {
    asm volatile("mbarrier.init.shared.b64 [%0], %1;" :: "r"(a), "r"(cnt) : "memory");
}

__device__ __forceinline__ void mbar_expect_tx(uint32_t a, unsigned bytes) {
    asm volatile("mbarrier.arrive.expect_tx.shared.b64 _, [%0], %1;"
                 :: "r"(a), "r"(bytes) : "memory");
}

__device__ __forceinline__ void mbar_wait(uint32_t a, unsigned parity) {
    asm volatile(
        "{\n\t.reg .pred P;\n\t"
        "WL%=:\n\t"
        "mbarrier.try_wait.parity.acquire.cta.shared::cta.b64 P, [%0], %1, 0x989680;\n\t"
        "@P bra.uni WD%=;\n\t"
        "bra.uni WL%=;\n\t"
        "WD%=:\n\t}"
        :: "r"(a), "r"(parity) : "memory");
}

__device__ __forceinline__ void bulk_g2s(uint32_t dst, const void* src,
                                         unsigned bytes, uint32_t mbar) {
    asm volatile(
        "cp.async.bulk.shared::cluster.global.mbarrier::complete_tx::bytes "
        "[%0], [%1], %2, [%3];"
        :: "r"(dst), "l"(src), "r"(bytes), "r"(mbar) : "memory");
}

__device__ __forceinline__ float sigm(float x) {
    return __fdividef(1.f, 1.f + __expf(-x));
}
__device__ __forceinline__ float tanh_f(float x) {
    float e = __expf(-2.f * fabsf(x));
    float t = __fdividef(1.f - e, 1.f + e);
    return copysignf(t, x);
}

// ---------------------------------------------------------------------------
// Persistent fused 2-layer LSTM — R12 structure + split-k dual warps/SMSP.
// Slot t: layer0 computes step t (t<TT); layer1 computes step t-1 (t>0).
//
// 8 warps: warp w handles k-half (w>=4), i.e. m in [half*64, half*64+64).
// Two warps share each SMSP -> stall windows (LDS latency, mbar wakeups,
// MUFU chains) are covered by the sibling warp instead of being exposed.
// Partial accumulators of half 1 are combined into half 0 via smem.
// Barrier / TMA chunk pipeline / fp16 h exchange identical to R12.
// ---------------------------------------------------------------------------
__global__ void __launch_bounds__(NT, 1) lstm_persistent(
    const float* __restrict__ Wh0, const float* __restrict__ Wx0,
    const float* __restrict__ b0,
    const float* __restrict__ Wx1, const float* __restrict__ Wh1,
    const float* __restrict__ b1)
{
    extern __shared__ char smem[];
    float* w0s = (float*)(smem + W0_OFF);
    float* wxs = (float*)(smem + WX_OFF);
    float* w1s = (float*)(smem + W1_OFF);
    ull*   red = (ull*)  (smem + RED_OFF);

    const uint32_t sbase   = smem_u32(smem);
    const uint32_t sh1_u32 = sbase + SH1_OFF;
    const uint32_t mbar_u  = sbase + MB_OFF;

    const int tid    = threadIdx.x;
    const int wg_tid = tid & 127;
    const int half   = tid >> 7;          // k-half: 0 -> m<64, 1 -> m>=64
    const int b      = wg_tid & 63;
    const int u      = wg_tid >> 6;
    const int j      = blockIdx.x * 2 + u;

    if (tid == 0) {
        #pragma unroll
        for (int c = 0; c < NCHUNK; ++c) mbar_init(mbar_u + c * 8, 1);
    }

    // Preload weight slices as k-pair float2 per gate:
    // w[(m*2+u)*4 + g] = { W[2m][g*256+j], W[2m+1][g*256+j] }
    for (int idx = tid; idx < 256; idx += NT) {
        const int m  = idx >> 1;
        const int uu = idx & 1;
        const int jj = blockIdx.x * 2 + uu;
        float2* d0 = (float2*)w0s + idx * 4;
        float2* dx = (float2*)wxs + idx * 4;
        float2* d1 = (float2*)w1s + idx * 4;
        const float* ra0 = Wh0 + (2 * m) * 1024;
        const float* rb0 = Wh0 + (2 * m + 1) * 1024;
        const float* rax = Wx1 + (2 * m) * 1024;
        const float* rbx = Wx1 + (2 * m + 1) * 1024;
        const float* ra1 = Wh1 + (2 * m) * 1024;
        const float* rb1 = Wh1 + (2 * m + 1) * 1024;
        #pragma unroll
        for (int g = 0; g < 4; ++g) {
            d0[g] = make_float2(ra0[g * 256 + jj], rb0[g * 256 + jj]);
            dx[g] = make_float2(rax[g * 256 + jj], rbx[g * 256 + jj]);
            d1[g] = make_float2(ra1[g * 256 + jj], rb1[g * 256 + jj]);
        }
    }
    // biases / x-weights only needed by half 0 (accumulator owner)
    float4 bia0 = make_float4(0.f, 0.f, 0.f, 0.f);
    float4 bia1 = bia0, wx0 = bia0;
    if (half == 0) {
        bia0 = make_float4(b0[j], b0[256 + j], b0[512 + j], b0[768 + j]);
        bia1 = make_float4(b1[j], b1[256 + j], b1[512 + j], b1[768 + j]);
        wx0  = make_float4(Wx0[j], Wx0[256 + j], Wx0[512 + j], Wx0[768 + j]);
    }

    float c0 = 0.f, c1 = 0.f, hsum = 0.f;
    __syncthreads();   // mbar init + weights visible

    // per-thread pointers: half2 pair (m,b) at pX[m*64] (uint view)
    const uint32_t* ph0 = (const uint32_t*)smem + b;
    const uint32_t* ph1 = (const uint32_t*)(smem + SH1_OFF) + b;
    const ulonglong2* pw0 = (const ulonglong2*)w0s + u * 2;   // [m*4], [m*4+1]
    const ulonglong2* pwx = (const ulonglong2*)wxs + u * 2;
    const ulonglong2* pw1 = (const ulonglong2*)w1s + u * 2;

    const int houti = (j >> 1) * 128 + b * 2 + (j & 1);
    const int mlo = half * 64;            // this half's m range: [mlo, mlo+64)
    const int clo = half * 2;             // chunks covering it: clo, clo+1

    for (int t = 0; t <= TT; ++t) {
        if (t > 0) {
            if (half == 0) __threadfence();   // publishers fence their h stores
            __syncthreads();                  // whole CTA done with previous slot
            if (tid == 0) {
                atomicAdd(&g_ct, 1u);
                const unsigned target = (unsigned)t * NCTA;
                while (*((volatile unsigned*)&g_ct) < target) { }
            }
            // other threads run ahead to the chunk mbar waits below
        }

        if (tid == 0) {
            asm volatile("fence.proxy.async;" ::: "memory");
            const unsigned short* s0 = g_h0[(t + 1) & 1];
            const unsigned short* s1 = g_h1[t & 1];
            #pragma unroll
            for (int c = 0; c < NCHUNK; ++c) {
                const uint32_t mb = mbar_u + c * 8;
                mbar_expect_tx(mb, 2 * CHUNK_BYTES);
                bulk_g2s(sbase   + c * CHUNK_BYTES, s0 + c * CHUNK_HALFS, CHUNK_BYTES, mb);
                bulk_g2s(sh1_u32 + c * CHUNK_BYTES, s1 + c * CHUNK_HALFS, CHUNK_BYTES, mb);
            }
        }

        // init gate accumulators (half 0 carries bias + x; half 1 zero)
        ull a0i, a0f, a0g, a0o, a1i, a1f, a1g, a1o;
        if (half == 0) {
            const float xv = (t < TT) ? g_xT[t * BB + b] : 0.f;
            a0i = pack2(fmaf(xv, wx0.x, bia0.x), 0.f);
            a0f = pack2(fmaf(xv, wx0.y, bia0.y), 0.f);
            a0g = pack2(fmaf(xv, wx0.z, bia0.z), 0.f);
            a0o = pack2(fmaf(xv, wx0.w, bia0.w), 0.f);
            a1i = pack2(bia1.x, 0.f);
            a1f = pack2(bia1.y, 0.f);
            a1g = pack2(bia1.z, 0.f);
            a1o = pack2(bia1.w, 0.f);
        } else {
            a0i = a0f = a0g = a0o = a1i = a1f = a1g = a1o = 0ull;
        }

        const unsigned par = (unsigned)(t & 1);
        #pragma unroll
        for (int cc = 0; cc < 2; ++cc) {
            const int c = clo + cc;
            mbar_wait(mbar_u + c * 8, par);
            const int mbase = c * M_PER_CHUNK;
            #pragma unroll 8
            for (int mm = 0; mm < M_PER_CHUNK; ++mm) {
                const int m = mbase + mm;
                const ull hv2  = h2_to_f32x2(ph0[m * 64]);
                const ull h1v2 = h2_to_f32x2(ph1[m * 64]);
                const ulonglong2 w0a = pw0[m * 4];
                const ulonglong2 w0b = pw0[m * 4 + 1];
                fma2(a0i, hv2, w0a.x); fma2(a0f, hv2, w0a.y);
                fma2(a0g, hv2, w0b.x); fma2(a0o, hv2, w0b.y);
                const ulonglong2 wxa = pwx[m * 4];
                const ulonglong2 wxb = pwx[m * 4 + 1];
                fma2(a1i, hv2, wxa.x); fma2(a1f, hv2, wxa.y);
                fma2(a1g, hv2, wxb.x); fma2(a1o, hv2, wxb.y);
                const ulonglong2 w1a = pw1[m * 4];
                const ulonglong2 w1b = pw1[m * 4 + 1];
                fma2(a1i, h1v2, w1a.x); fma2(a1f, h1v2, w1a.y);
                fma2(a1g, h1v2, w1b.x); fma2(a1o, h1v2, w1b.y);
            }
        }

        // combine the two k-halves: half 1 publishes, half 0 accumulates
        if (half == 1) {
            ull* r = red + wg_tid * 8;
            r[0] = a0i; r[1] = a0f; r[2] = a0g; r[3] = a0o;
            r[4] = a1i; r[5] = a1f; r[6] = a1g; r[7] = a1o;
        }
        __syncthreads();

        if (half == 0) {
            const ull* r = red + wg_tid * 8;
            add2(a0i, r[0]); add2(a0f, r[1]); add2(a0g, r[2]); add2(a0o, r[3]);
            add2(a1i, r[4]); add2(a1f, r[5]); add2(a1g, r[6]); add2(a1o, r[7]);

            if (t < TT) {   // layer0 step t
                const float ig = sigm(hadd2(a0i));
                const float fg = sigm(hadd2(a0f));
                const float gg = tanh_f(hadd2(a0g));
                const float og = sigm(hadd2(a0o));
                c0 = fmaf(fg, c0, ig * gg);
                st_h16(&g_h0[t & 1][houti], og * tanh_f(c0));
            }
            if (t > 0) {    // layer1 step t-1
                const float ig = sigm(hadd2(a1i));
                const float fg = sigm(hadd2(a1f));
                const float gg = tanh_f(hadd2(a1g));
                const float og = sigm(hadd2(a1o));
                c1 = fmaf(fg, c1, ig * gg);
                const float h1n = og * tanh_f(c1);
                hsum += h1n;
                if (t < TT) st_h16(&g_h1[(t + 1) & 1][houti], h1n);
            }
        }
    }

    if (half == 0) g_hmean[j * 64 + b] = hsum * (1.f / 1024.f);
}

// ---------------------------------------------------------------------------
// Head: theta projection, concat, 3x (dense + ELU), final dense. Runs once.
// ---------------------------------------------------------------------------
__global__ void final_kernel(
    const float* __restrict__ theta,
    const float* __restrict__ pW, const float* __restrict__ pb,
    const float* __restrict__ l0W, const float* __restrict__ l0b,
    const float* __restrict__ l1W, const float* __restrict__ l1b,
    const float* __restrict__ l2W, const float* __restrict__ l2b,
    const float* __restrict__ oW,  const float* __restrict__ ob,
    float* __restrict__ out)
{
    __shared__ float hin[512];
    __shared__ float act0[256];
    __shared__ float act1[256];
    __shared__ float act2[128];
    const int bb = blockIdx.x;
    const int tj = threadIdx.x;

    hin[tj] = g_hmean[tj * 64 + bb];
    {
        float s = pb[tj];
        #pragma unroll
        for (int d = 0; d < 5; ++d) s = fmaf(theta[bb * 5 + d], pW[d * 256 + tj], s);
        hin[256 + tj] = s;
    }
    __syncthreads();
    {
        float acc = l0b[tj];
        for (int k = 0; k < 512; ++k) acc = fmaf(hin[k], l0W[k * 256 + tj], acc);
        act0[tj] = acc > 0.f ? acc : expm1f(acc);
    }
    __syncthreads();
    {
        float acc = l1b[tj];
        for (int k = 0; k < 256; ++k) acc = fmaf(act0[k], l1W[k * 256 + tj], acc);
        act1[tj] = acc > 0.f ? acc : expm1f(acc);
    }
    __syncthreads();
    if (tj < 128) {
        float acc = l2b[tj];
        for (int k = 0; k < 256; ++k) acc = fmaf(act1[k], l2W[k * 128 + tj], acc);
        act2[tj] = acc > 0.f ? acc : expm1f(acc);
    }
    __syncthreads();
    if (tj == 0) {
        float s = ob[0];
        for (int k = 0; k < 128; ++k) s = fmaf(act2[k], oW[k], s);
        out[bb] = s;
    }
}

// ---------------------------------------------------------------------------
extern "C" void kernel_launch(void* const* d_in, const int* in_sizes, int n_in,
                              void* d_out, int out_size) {
    const float* x     = (const float*)d_in[0];
    const float* theta = (const float*)d_in[1];
    const float* Wx0   = (const float*)d_in[2];
    const float* Wh0   = (const float*)d_in[3];
    const float* b0    = (const float*)d_in[4];
    const float* Wx1   = (const float*)d_in[5];
    const float* Wh1   = (const float*)d_in[6];
    const float* b1    = (const float*)d_in[7];
    const float* pW    = (const float*)d_in[8];
    const float* pb    = (const float*)d_in[9];
    const float* l0W   = (const float*)d_in[10];
    const float* l0b   = (const float*)d_in[11];
    const float* l1W   = (const float*)d_in[12];
    const float* l1b   = (const float*)d_in[13];
    const float* l2W   = (const float*)d_in[14];
    const float* l2b   = (const float*)d_in[15];
    const float* oW    = (const float*)d_in[16];
    const float* ob    = (const float*)d_in[17];

    cudaFuncSetAttribute(lstm_persistent,
                         cudaFuncAttributeMaxDynamicSharedMemorySize, SMEM_SZ);

    init_kernel<<<(TT * BB + 255) / 256, 256>>>(x);
    lstm_persistent<<<NCTA, NT, SMEM_SZ>>>(Wh0, Wx0, b0, Wx1, Wh1, b1);
    final_kernel<<<BB, 256>>>(theta, pW, pb, l0W, l0b, l1W, l1b,
                              l2W, l2b, oW, ob, (float*)d_out);
}